// round 2
// baseline (speedup 1.0000x reference)
#include <cuda_runtime.h>

// ---------------------------------------------------------------------------
// DagEncoder: h2 = relu(relu([x|h_node] W1 + b1) W2 + b2) per node,
// segment-sum h2 over ptr, then out = seg_h2 @ W3 + len * b3.
// Layer 3 is linear => commutes with the segment sum (24% FLOP reduction).
//
// ptr arrives as EITHER int64 or int32 (JAX x64-disabled downcast); a prep
// kernel detects the dtype and normalizes into g_ptr (int32).
// ---------------------------------------------------------------------------

#define MAX_DAGS 20000

__device__ float g_acc[MAX_DAGS * 64];   // per-DAG hidden sums [num_dags, 64]
__device__ int   g_ptr[MAX_DAGS + 1];    // normalized segment boundaries

typedef unsigned long long u64;

__device__ __forceinline__ u64 pack2(float x, float y) {
    u64 r;
    asm("mov.b64 %0, {%1, %2};" : "=l"(r) : "f"(x), "f"(y));
    return r;
}
__device__ __forceinline__ void unpack2(u64 v, float &x, float &y) {
    asm("mov.b64 {%0, %1}, %2;" : "=f"(x), "=f"(y) : "l"(v));
}
// Packed dual-FP32 FMA (sm_100+): one issue slot, two fp32 FMAs.
__device__ __forceinline__ u64 ffma2(u64 a, u64 b, u64 c) {
    u64 d;
    asm("fma.rn.f32x2 %0, %1, %2, %3;" : "=l"(d) : "l"(a), "l"(b), "l"(c));
    return d;
}

// ---------------------------------------------------------------------------
// Prep: detect ptr dtype (int32 vs int64) and normalize; zero the accumulator.
// Detection: p32[num_dags]==num_nodes can ONLY hold if data is int32 (if data
// were int64, that word is an interior boundary value, strictly < num_nodes).
// Reading p32[num_dags] is in-bounds under either dtype.
// ---------------------------------------------------------------------------
__global__ void prep_kernel(const void* __restrict__ ptr_raw,
                            int num_dags, int num_nodes) {
    const int*       p32 = (const int*)ptr_raw;
    const long long* p64 = (const long long*)ptr_raw;
    const bool is32 = (p32[num_dags] == num_nodes);

    const int stride = blockDim.x * gridDim.x;
    for (int i = blockIdx.x * blockDim.x + threadIdx.x;
         i <= num_dags; i += stride)
        g_ptr[i] = is32 ? p32[i] : (int)p64[i];

    for (int i = blockIdx.x * blockDim.x + threadIdx.x;
         i < num_dags * 64; i += stride)
        g_acc[i] = 0.0f;
}

// ---------------------------------------------------------------------------
// Main fused kernel: 128 threads, one node per thread.
// ---------------------------------------------------------------------------
__global__ __launch_bounds__(128) void mlp_seg_kernel(
    const float* __restrict__ h_node,   // [N, 32]
    const float* __restrict__ x,        // [N, 5]
    const float* __restrict__ W1,       // [37, 64]
    const float* __restrict__ b1,       // [64]
    const float* __restrict__ W2,       // [64, 64]
    const float* __restrict__ b2,       // [64]
    int num_nodes, int num_dags)
{
    __shared__ __align__(16) float sW1[37 * 64];
    __shared__ __align__(16) float sW2[64 * 64];
    __shared__ __align__(16) float sB1[64];
    __shared__ __align__(16) float sB2[64];

    const int tid = threadIdx.x;
    for (int i = tid; i < 37 * 64; i += 128) sW1[i] = W1[i];
    for (int i = tid; i < 64 * 64; i += 128) sW2[i] = W2[i];
    if (tid < 64) { sB1[tid] = b1[tid]; sB2[tid] = b2[tid]; }
    __syncthreads();

    const int node  = blockIdx.x * 128 + tid;
    const bool valid = node < num_nodes;

    // ---- load inputs: in[0..4] = x, in[5..36] = h_node ----
    float in[37];
    if (valid) {
        const float* xs = x + (size_t)node * 5;
#pragma unroll
        for (int i = 0; i < 5; i++) in[i] = xs[i];
        const float4* hv = (const float4*)(h_node + (size_t)node * 32);
#pragma unroll
        for (int i = 0; i < 8; i++) {
            float4 v = hv[i];
            in[5 + 4 * i] = v.x; in[6 + 4 * i] = v.y;
            in[7 + 4 * i] = v.z; in[8 + 4 * i] = v.w;
        }
    } else {
#pragma unroll
        for (int i = 0; i < 37; i++) in[i] = 0.0f;
    }

    // ---- segment id: upper_bound(g_ptr, node) - 1 (handles empty segs) ----
    int seg = -1;
    if (valid) {
        int l = 1, r = num_dags;  // first j in [1, num_dags] with g_ptr[j] > node
        while (l < r) {
            int m = (l + r) >> 1;
            if (g_ptr[m] > node) r = m; else l = m + 1;
        }
        seg = l - 1;
    }

    // ---- layer 1: h1 = relu(in @ W1 + b1), acc[j] packs (h=2j, h=2j+1) ----
    float h1[64];
    {
        u64 acc[32];
        const ulonglong2* bv = (const ulonglong2*)sB1;
#pragma unroll
        for (int q = 0; q < 16; q++) {
            ulonglong2 b = bv[q];
            acc[2 * q] = b.x; acc[2 * q + 1] = b.y;
        }
#pragma unroll
        for (int k = 0; k < 37; k++) {
            u64 vv = pack2(in[k], in[k]);
            const ulonglong2* wrow = ((const ulonglong2*)sW1) + k * 16;
#pragma unroll
            for (int q = 0; q < 16; q++) {
                ulonglong2 w = wrow[q];
                acc[2 * q]     = ffma2(vv, w.x, acc[2 * q]);
                acc[2 * q + 1] = ffma2(vv, w.y, acc[2 * q + 1]);
            }
        }
#pragma unroll
        for (int j = 0; j < 32; j++) {
            float a, b;
            unpack2(acc[j], a, b);
            h1[2 * j]     = fmaxf(a, 0.0f);
            h1[2 * j + 1] = fmaxf(b, 0.0f);
        }
    }

    // ---- layer 2: h2 = relu(h1 @ W2 + b2) ----
    float h2[64];
    {
        u64 acc[32];
        const ulonglong2* bv = (const ulonglong2*)sB2;
#pragma unroll
        for (int q = 0; q < 16; q++) {
            ulonglong2 b = bv[q];
            acc[2 * q] = b.x; acc[2 * q + 1] = b.y;
        }
#pragma unroll
        for (int k = 0; k < 64; k++) {
            u64 vv = pack2(h1[k], h1[k]);
            const ulonglong2* wrow = ((const ulonglong2*)sW2) + k * 16;
#pragma unroll
            for (int q = 0; q < 16; q++) {
                ulonglong2 w = wrow[q];
                acc[2 * q]     = ffma2(vv, w.x, acc[2 * q]);
                acc[2 * q + 1] = ffma2(vv, w.y, acc[2 * q + 1]);
            }
        }
#pragma unroll
        for (int j = 0; j < 32; j++) {
            float a, b;
            unpack2(acc[j], a, b);
            h2[2 * j]     = fmaxf(a, 0.0f);
            h2[2 * j + 1] = fmaxf(b, 0.0f);
        }
    }

    // ---- warp-level segmented suffix reduction + one RED per (warp, seg) ----
    const unsigned mask = 0xffffffffu;
    const int lane = tid & 31;

    int s_up = __shfl_up_sync(mask, seg, 1);
    bool head = (seg >= 0) && (lane == 0 || s_up != seg);

    int s1  = __shfl_down_sync(mask, seg, 1);
    int s2  = __shfl_down_sync(mask, seg, 2);
    int s4  = __shfl_down_sync(mask, seg, 4);
    int s8  = __shfl_down_sync(mask, seg, 8);
    int s16 = __shfl_down_sync(mask, seg, 16);
    bool c1  = (lane + 1  < 32) && (s1  == seg);
    bool c2  = (lane + 2  < 32) && (s2  == seg);
    bool c4  = (lane + 4  < 32) && (s4  == seg);
    bool c8  = (lane + 8  < 32) && (s8  == seg);
    bool c16 = (lane + 16 < 32) && (s16 == seg);

#pragma unroll
    for (int h = 0; h < 64; h++) {
        float v = valid ? h2[h] : 0.0f;
        float o;
        o = __shfl_down_sync(mask, v, 1);  if (c1)  v += o;
        o = __shfl_down_sync(mask, v, 2);  if (c2)  v += o;
        o = __shfl_down_sync(mask, v, 4);  if (c4)  v += o;
        o = __shfl_down_sync(mask, v, 8);  if (c8)  v += o;
        o = __shfl_down_sync(mask, v, 16); if (c16) v += o;
        if (head) atomicAdd(&g_acc[(size_t)seg * 64 + h], v);
    }
}

// ---------------------------------------------------------------------------
// Epilogue: out[d] = g_acc[d] @ W3 + len(d) * b3.  8 dags per 256-thr block.
// ---------------------------------------------------------------------------
__global__ __launch_bounds__(256) void final_kernel(
    const float* __restrict__ W3,       // [64, 32]
    const float* __restrict__ b3,       // [32]
    float* __restrict__ out,            // [num_dags, 32]
    int num_dags)
{
    __shared__ __align__(16) float sW3[64 * 32];
    __shared__ float sB3[32];
    const int tid = threadIdx.x;
    for (int i = tid; i < 64 * 32; i += 256) sW3[i] = W3[i];
    if (tid < 32) sB3[tid] = b3[tid];
    __syncthreads();

    const int d = blockIdx.x * 8 + (tid >> 5);
    const int e = tid & 31;
    if (d >= num_dags) return;

    const float cnt = (float)(g_ptr[d + 1] - g_ptr[d]);
    float acc = cnt * sB3[e];
    const float* gd = &g_acc[(size_t)d * 64];
#pragma unroll
    for (int k = 0; k < 64; k++)
        acc = fmaf(gd[k], sW3[k * 32 + e], acc);
    out[(size_t)d * 32 + e] = acc;
}

// ---------------------------------------------------------------------------
extern "C" void kernel_launch(void* const* d_in, const int* in_sizes, int n_in,
                              void* d_out, int out_size)
{
    const float* h_node = (const float*)d_in[0];
    const float* x      = (const float*)d_in[1];
    const float* W1     = (const float*)d_in[2];
    const float* b1     = (const float*)d_in[3];
    const float* W2     = (const float*)d_in[4];
    const float* b2     = (const float*)d_in[5];
    const float* W3     = (const float*)d_in[6];
    const float* b3     = (const float*)d_in[7];
    const void*  ptr    = (const void*)d_in[8];

    const int num_nodes = in_sizes[0] / 32;
    const int num_dags  = in_sizes[8] - 1;

    prep_kernel<<<160, 512>>>(ptr, num_dags, num_nodes);

    mlp_seg_kernel<<<(num_nodes + 127) / 128, 128>>>(
        h_node, x, W1, b1, W2, b2, num_nodes, num_dags);

    final_kernel<<<(num_dags + 7) / 8, 256>>>(
        W3, b3, (float*)d_out, num_dags);
}

// round 5
// speedup vs baseline: 2.9702x; 2.9702x over previous
#include <cuda_runtime.h>
#include <cuda_bf16.h>

// DagEncoder via warp-level mma.sync (bf16 hi/lo split, 3-term) — baseline
// PTX only (compute_103 has no tcgen05). Segment-sum via indicator MMA.
// Layer 3 commutes with the segment sum -> applied on per-DAG sums.

#define MAX_DAGS 20000
__device__ float g_acc[MAX_DAGS * 64];
__device__ int   g_ptr[MAX_DAGS + 1];

typedef unsigned int u32;

__device__ __forceinline__ u32 smem_u32(const void* p) {
    u32 a;
    asm("{ .reg .u64 t; cvta.to.shared.u64 t, %1; cvt.u32.u64 %0, t; }"
        : "=r"(a) : "l"(p));
    return a;
}
// pack two f32 -> bf16x2 (v0 low half, v1 high half)
__device__ __forceinline__ u32 bf16pair(float v0, float v1) {
    u32 d;
    asm("cvt.rn.bf16x2.f32 %0, %1, %2;" : "=r"(d) : "f"(v1), "f"(v0));
    return d;
}
__device__ __forceinline__ void split2(float v0, float v1, u32& hi, u32& lo) {
    hi = bf16pair(v0, v1);
    float h0 = __uint_as_float(hi << 16);
    float h1 = __uint_as_float(hi & 0xffff0000u);
    lo = bf16pair(v0 - h0, v1 - h1);
}
__device__ __forceinline__ void ldsm_x4(u32 a, u32* r) {
    asm volatile("ldmatrix.sync.aligned.m8n8.x4.shared.b16 {%0,%1,%2,%3}, [%4];"
        : "=r"(r[0]), "=r"(r[1]), "=r"(r[2]), "=r"(r[3]) : "r"(a));
}
__device__ __forceinline__ void ldsm_x4t(u32 a, u32* r) {
    asm volatile("ldmatrix.sync.aligned.m8n8.x4.trans.shared.b16 {%0,%1,%2,%3}, [%4];"
        : "=r"(r[0]), "=r"(r[1]), "=r"(r[2]), "=r"(r[3]) : "r"(a));
}
__device__ __forceinline__ void mma_bf16(float* d, const u32* a, u32 b0, u32 b1) {
    asm("mma.sync.aligned.m16n8k16.row.col.f32.bf16.bf16.f32 "
        "{%0,%1,%2,%3},{%4,%5,%6,%7},{%8,%9},{%0,%1,%2,%3};"
        : "+f"(d[0]), "+f"(d[1]), "+f"(d[2]), "+f"(d[3])
        : "r"(a[0]), "r"(a[1]), "r"(a[2]), "r"(a[3]), "r"(b0), "r"(b1));
}

__global__ void prep_kernel(const void* __restrict__ ptr_raw,
                            int num_dags, int num_nodes) {
    const int*       p32 = (const int*)ptr_raw;
    const long long* p64 = (const long long*)ptr_raw;
    const bool is32 = (p32[num_dags] == num_nodes);
    const int stride = blockDim.x * gridDim.x;
    for (int i = blockIdx.x * blockDim.x + threadIdx.x; i <= num_dags; i += stride)
        g_ptr[i] = is32 ? p32[i] : (int)p64[i];
    for (int i = blockIdx.x * blockDim.x + threadIdx.x; i < num_dags * 64; i += stride)
        g_acc[i] = 0.0f;
}

// dynamic smem layout:
//   W1h[48][72]b16 @0 (6912)  W1l @6912   (rows k, cols n, pad->0)
//   W2h[64][72]b16 @13824 (9216)  W2l @23040
//   b1 f32[64] @32256, b2 @32512
//   per-warp scratch 9216B @32768 + w*9216:
//     A1 hi[32][56]b16 @0, lo @3584 ; A2/h2 hi[32][72] @0, lo @4608
#define OFF_W1H 0
#define OFF_W1L 6912
#define OFF_W2H 13824
#define OFF_W2L 23040
#define OFF_B1  32256
#define OFF_B2  32512
#define OFF_SCR 32768
#define SCR_WARP 9216
#define SMEM_SZ (OFF_SCR + 4 * SCR_WARP)

__global__ __launch_bounds__(128) void mma_seg_kernel(
    const float* __restrict__ h_node, const float* __restrict__ x,
    const float* __restrict__ W1, const float* __restrict__ b1,
    const float* __restrict__ W2, const float* __restrict__ b2,
    int num_nodes, int num_dags, int ntiles)
{
    extern __shared__ __align__(16) unsigned char sm[];
    __shared__ int sRank[4][32];

    const int tid = threadIdx.x, lane = tid & 31, w = tid >> 5;

    for (int i = tid; i < 48 * 72; i += 128) {
        int k = i / 72, n = i % 72;
        float v = (k < 37 && n < 64) ? W1[k * 64 + n] : 0.0f;
        __nv_bfloat16 h = __float2bfloat16_rn(v);
        *(__nv_bfloat16*)(sm + OFF_W1H + i * 2) = h;
        *(__nv_bfloat16*)(sm + OFF_W1L + i * 2) =
            __float2bfloat16_rn(v - __bfloat162float(h));
    }
    for (int i = tid; i < 64 * 72; i += 128) {
        int k = i / 72, n = i % 72;
        float v = (n < 64) ? W2[k * 64 + n] : 0.0f;
        __nv_bfloat16 h = __float2bfloat16_rn(v);
        *(__nv_bfloat16*)(sm + OFF_W2H + i * 2) = h;
        *(__nv_bfloat16*)(sm + OFF_W2L + i * 2) =
            __float2bfloat16_rn(v - __bfloat162float(h));
    }
    if (tid < 64) {
        ((float*)(sm + OFF_B1))[tid] = b1[tid];
        ((float*)(sm + OFF_B2))[tid] = b2[tid];
    }
    __syncthreads();

    unsigned char* scrp = sm + OFF_SCR + w * SCR_WARP;
    const u32 scr = smem_u32(scrp);
    const u32 w1h = smem_u32(sm + OFF_W1H);
    const u32 w2h = smem_u32(sm + OFF_W2H);
    const float* B1s = (const float*)(sm + OFF_B1);
    const float* B2s = (const float*)(sm + OFF_B2);

    const int g = lane >> 2, t = lane & 3;
    const int lrow = lane & 15, lcs = lane >> 4;
    const unsigned FULL = 0xffffffffu;
    const int wid_g = blockIdx.x * 4 + w, nW = gridDim.x * 4;

    for (int tile = wid_g; tile < ntiles; tile += nW) {
        const int node0 = tile * 32;
        const int node = node0 + lane;
        const bool valid = node < num_nodes;

        float vals[48];
#pragma unroll
        for (int i = 0; i < 48; i++) vals[i] = 0.0f;
        if (valid) {
            const float* xp = x + (size_t)node * 5;
#pragma unroll
            for (int i = 0; i < 5; i++) vals[i] = xp[i];
            const float4* hp = (const float4*)(h_node + (size_t)node * 32);
#pragma unroll
            for (int i = 0; i < 8; i++) {
                float4 v4 = hp[i];
                vals[5 + 4 * i] = v4.x; vals[6 + 4 * i] = v4.y;
                vals[7 + 4 * i] = v4.z; vals[8 + 4 * i] = v4.w;
            }
        }
        int seg = -1;
        if (valid) {
            int l = 1, r = num_dags;
            while (l < r) { int m = (l + r) >> 1; if (g_ptr[m] > node) r = m; else l = m + 1; }
            seg = l - 1;
        }

        __syncwarp();  // scratch reuse vs previous iteration
        {
            u32 hi[24], lo[24];
#pragma unroll
            for (int j = 0; j < 24; j++) split2(vals[2 * j], vals[2 * j + 1], hi[j], lo[j]);
            uint4* dh = (uint4*)(scrp + lane * 112);
            uint4* dl = (uint4*)(scrp + 3584 + lane * 112);
#pragma unroll
            for (int j = 0; j < 6; j++) {
                dh[j] = make_uint4(hi[4*j], hi[4*j+1], hi[4*j+2], hi[4*j+3]);
                dl[j] = make_uint4(lo[4*j], lo[4*j+1], lo[4*j+2], lo[4*j+3]);
            }
        }
        __syncwarp();

        // ---- layer 1: M32 K48 N64 ----
        u32 a1h[2][3][4], a1l[2][3][4];
#pragma unroll
        for (int mt = 0; mt < 2; mt++)
#pragma unroll
            for (int kt = 0; kt < 3; kt++) {
                u32 ad = scr + (mt * 16 + lrow) * 112 + (kt * 16 + lcs * 8) * 2;
                ldsm_x4(ad, a1h[mt][kt]);
                ldsm_x4(ad + 3584, a1l[mt][kt]);
            }
        __syncwarp();

#pragma unroll
        for (int half = 0; half < 2; half++) {
            float d[2][4][4];
#pragma unroll
            for (int ntl = 0; ntl < 4; ntl++) {
                float2 bb = *(const float2*)(B1s + (half * 4 + ntl) * 8 + 2 * t);
#pragma unroll
                for (int mt = 0; mt < 2; mt++) {
                    d[mt][ntl][0] = bb.x; d[mt][ntl][1] = bb.y;
                    d[mt][ntl][2] = bb.x; d[mt][ntl][3] = bb.y;
                }
            }
#pragma unroll
            for (int np = 0; np < 2; np++) {
                int npg = half * 2 + np;
                u32 bh[3][4], bl[3][4];
#pragma unroll
                for (int kt = 0; kt < 3; kt++) {
                    u32 ad = w1h + (kt * 16 + lrow) * 144 + (npg * 16 + lcs * 8) * 2;
                    ldsm_x4t(ad, bh[kt]);
                    ldsm_x4t(ad + (OFF_W1L - OFF_W1H), bl[kt]);
                }
#pragma unroll
                for (int mt = 0; mt < 2; mt++)
#pragma unroll
                    for (int kt = 0; kt < 3; kt++)
#pragma unroll
                        for (int hh = 0; hh < 2; hh++) {
                            float* dd = d[mt][np * 2 + hh];
                            mma_bf16(dd, a1h[mt][kt], bh[kt][2*hh], bh[kt][2*hh+1]);
                            mma_bf16(dd, a1h[mt][kt], bl[kt][2*hh], bl[kt][2*hh+1]);
                            mma_bf16(dd, a1l[mt][kt], bh[kt][2*hh], bh[kt][2*hh+1]);
                        }
            }
#pragma unroll
            for (int mt = 0; mt < 2; mt++)
#pragma unroll
                for (int ntl = 0; ntl < 4; ntl++) {
                    int c = (half * 4 + ntl) * 8 + 2 * t;
                    int r0 = mt * 16 + g, r1 = r0 + 8;
                    u32 p0, q0, p1, q1;
                    split2(fmaxf(d[mt][ntl][0], 0.f), fmaxf(d[mt][ntl][1], 0.f), p0, q0);
                    split2(fmaxf(d[mt][ntl][2], 0.f), fmaxf(d[mt][ntl][3], 0.f), p1, q1);
                    *(u32*)(scrp + r0 * 144 + c * 2) = p0;
                    *(u32*)(scrp + 4608 + r0 * 144 + c * 2) = q0;
                    *(u32*)(scrp + r1 * 144 + c * 2) = p1;
                    *(u32*)(scrp + 4608 + r1 * 144 + c * 2) = q1;
                }
        }
        __syncwarp();

        // ---- layer 2: M32 K64 N64; output h2 back to scratch ----
        u32 a2h[2][4][4], a2l[2][4][4];
#pragma unroll
        for (int mt = 0; mt < 2; mt++)
#pragma unroll
            for (int kt = 0; kt < 4; kt++) {
                u32 ad = scr + (mt * 16 + lrow) * 144 + (kt * 16 + lcs * 8) * 2;
                ldsm_x4(ad, a2h[mt][kt]);
                ldsm_x4(ad + 4608, a2l[mt][kt]);
            }
        __syncwarp();

#pragma unroll
        for (int half = 0; half < 2; half++) {
            float d[2][4][4];
#pragma unroll
            for (int ntl = 0; ntl < 4; ntl++) {
                float2 bb = *(const float2*)(B2s + (half * 4 + ntl) * 8 + 2 * t);
#pragma unroll
                for (int mt = 0; mt < 2; mt++) {
                    d[mt][ntl][0] = bb.x; d[mt][ntl][1] = bb.y;
                    d[mt][ntl][2] = bb.x; d[mt][ntl][3] = bb.y;
                }
            }
#pragma unroll
            for (int np = 0; np < 2; np++) {
                int npg = half * 2 + np;
                u32 bh[4][4], bl[4][4];
#pragma unroll
                for (int kt = 0; kt < 4; kt++) {
                    u32 ad = w2h + (kt * 16 + lrow) * 144 + (npg * 16 + lcs * 8) * 2;
                    ldsm_x4t(ad, bh[kt]);
                    ldsm_x4t(ad + (OFF_W2L - OFF_W2H), bl[kt]);
                }
#pragma unroll
                for (int mt = 0; mt < 2; mt++)
#pragma unroll
                    for (int kt = 0; kt < 4; kt++)
#pragma unroll
                        for (int hh = 0; hh < 2; hh++) {
                            float* dd = d[mt][np * 2 + hh];
                            mma_bf16(dd, a2h[mt][kt], bh[kt][2*hh], bh[kt][2*hh+1]);
                            mma_bf16(dd, a2h[mt][kt], bl[kt][2*hh], bl[kt][2*hh+1]);
                            mma_bf16(dd, a2l[mt][kt], bh[kt][2*hh], bh[kt][2*hh+1]);
                        }
            }
#pragma unroll
            for (int mt = 0; mt < 2; mt++)
#pragma unroll
                for (int ntl = 0; ntl < 4; ntl++) {
                    int c = (half * 4 + ntl) * 8 + 2 * t;
                    int r0 = mt * 16 + g, r1 = r0 + 8;
                    bool ok0 = (node0 + r0) < num_nodes, ok1 = (node0 + r1) < num_nodes;
                    float v0 = ok0 ? fmaxf(d[mt][ntl][0], 0.f) : 0.f;
                    float v1 = ok0 ? fmaxf(d[mt][ntl][1], 0.f) : 0.f;
                    float v2 = ok1 ? fmaxf(d[mt][ntl][2], 0.f) : 0.f;
                    float v3 = ok1 ? fmaxf(d[mt][ntl][3], 0.f) : 0.f;
                    u32 p0, q0, p1, q1;
                    split2(v0, v1, p0, q0);
                    split2(v2, v3, p1, q1);
                    *(u32*)(scrp + r0 * 144 + c * 2) = p0;
                    *(u32*)(scrp + 4608 + r0 * 144 + c * 2) = q0;
                    *(u32*)(scrp + r1 * 144 + c * 2) = p1;
                    *(u32*)(scrp + 4608 + r1 * 144 + c * 2) = q1;
                }
        }
        __syncwarp();

        // ---- segment ranks + indicator fragments ----
        int segup = __shfl_up_sync(FULL, seg, 1);
        bool head = valid && (lane == 0 || segup != seg);
        unsigned bm = __ballot_sync(FULL, head);
        int rank = __popc(bm & (0xffffffffu >> (31 - lane))) - 1;
        int nsegs = __popc(bm);
        if (head) sRank[w][rank] = seg;
        __syncwarp();

        int rk[2][4];
#pragma unroll
        for (int kt = 0; kt < 2; kt++) {
            rk[kt][0] = __shfl_sync(FULL, rank, kt * 16 + 2 * t);
            rk[kt][1] = __shfl_sync(FULL, rank, kt * 16 + 2 * t + 1);
            rk[kt][2] = __shfl_sync(FULL, rank, kt * 16 + 8 + 2 * t);
            rk[kt][3] = __shfl_sync(FULL, rank, kt * 16 + 8 + 2 * t + 1);
        }
        const int nmt = (nsegs > 16) ? 2 : 1;
        u32 ia[2][2][4];
#pragma unroll
        for (int mt = 0; mt < 2; mt++)
#pragma unroll
            for (int kt = 0; kt < 2; kt++) {
                int R0 = mt * 16 + g, R1 = R0 + 8;
                ia[mt][kt][0] = (rk[kt][0]==R0 ? 0x3F80u:0u) | (rk[kt][1]==R0 ? 0x3F800000u:0u);
                ia[mt][kt][1] = (rk[kt][0]==R1 ? 0x3F80u:0u) | (rk[kt][1]==R1 ? 0x3F800000u:0u);
                ia[mt][kt][2] = (rk[kt][2]==R0 ? 0x3F80u:0u) | (rk[kt][3]==R0 ? 0x3F800000u:0u);
                ia[mt][kt][3] = (rk[kt][2]==R1 ? 0x3F80u:0u) | (rk[kt][3]==R1 ? 0x3F800000u:0u);
            }

        // ---- reduction MMA: D[rank][n] = I @ h2 (hi + lo terms) ----
        float dr[2][8][4];
#pragma unroll
        for (int mt = 0; mt < 2; mt++)
#pragma unroll
            for (int ntl = 0; ntl < 8; ntl++)
#pragma unroll
                for (int q = 0; q < 4; q++) dr[mt][ntl][q] = 0.0f;

#pragma unroll
        for (int np = 0; np < 4; np++) {
            u32 bh[2][4], bl[2][4];
#pragma unroll
            for (int kt = 0; kt < 2; kt++) {
                u32 ad = scr + (kt * 16 + lrow) * 144 + (np * 16 + lcs * 8) * 2;
                ldsm_x4t(ad, bh[kt]);
                ldsm_x4t(ad + 4608, bl[kt]);
            }
            for (int mt = 0; mt < nmt; mt++)
#pragma unroll
                for (int kt = 0; kt < 2; kt++)
#pragma unroll
                    for (int hh = 0; hh < 2; hh++) {
                        float* dd = dr[mt][np * 2 + hh];
                        mma_bf16(dd, ia[mt][kt], bh[kt][2*hh], bh[kt][2*hh+1]);
                        mma_bf16(dd, ia[mt][kt], bl[kt][2*hh], bl[kt][2*hh+1]);
                    }
        }

        // ---- scatter per-segment sums ----
        for (int mt = 0; mt < nmt; mt++)
#pragma unroll
            for (int ntl = 0; ntl < 8; ntl++) {
                int c = ntl * 8 + 2 * t;
                int R0 = mt * 16 + g, R1 = R0 + 8;
                if (R0 < nsegs) {
                    float* p = &g_acc[(size_t)sRank[w][R0] * 64 + c];
                    atomicAdd(p, dr[mt][ntl][0]);
                    atomicAdd(p + 1, dr[mt][ntl][1]);
                }
                if (R1 < nsegs) {
                    float* p = &g_acc[(size_t)sRank[w][R1] * 64 + c];
                    atomicAdd(p, dr[mt][ntl][2]);
                    atomicAdd(p + 1, dr[mt][ntl][3]);
                }
            }
    }
}

__global__ __launch_bounds__(256) void final_kernel(
    const float* __restrict__ W3, const float* __restrict__ b3,
    float* __restrict__ out, int num_dags)
{
    __shared__ __align__(16) float sW3[64 * 32];
    __shared__ float sB3[32];
    const int tid = threadIdx.x;
    for (int i = tid; i < 64 * 32; i += 256) sW3[i] = W3[i];
    if (tid < 32) sB3[tid] = b3[tid];
    __syncthreads();

    const int d = blockIdx.x * 8 + (tid >> 5);
    const int e = tid & 31;
    if (d >= num_dags) return;

    const float cnt = (float)(g_ptr[d + 1] - g_ptr[d]);
    float acc = cnt * sB3[e];
    const float* gd = &g_acc[(size_t)d * 64];
#pragma unroll
    for (int k = 0; k < 64; k++)
        acc = fmaf(gd[k], sW3[k * 32 + e], acc);
    out[(size_t)d * 32 + e] = acc;
}

extern "C" void kernel_launch(void* const* d_in, const int* in_sizes, int n_in,
                              void* d_out, int out_size)
{
    const float* h_node = (const float*)d_in[0];
    const float* x      = (const float*)d_in[1];
    const float* W1     = (const float*)d_in[2];
    const float* b1     = (const float*)d_in[3];
    const float* W2     = (const float*)d_in[4];
    const float* b2     = (const float*)d_in[5];
    const float* W3     = (const float*)d_in[6];
    const float* b3     = (const float*)d_in[7];
    const void*  ptr    = (const void*)d_in[8];

    const int num_nodes = in_sizes[0] / 32;
    const int num_dags  = in_sizes[8] - 1;
    const int ntiles    = (num_nodes + 31) / 32;

    prep_kernel<<<160, 512>>>(ptr, num_dags, num_nodes);

    static int smem_set = 0;
    if (!smem_set) {
        cudaFuncSetAttribute(mma_seg_kernel,
                             cudaFuncAttributeMaxDynamicSharedMemorySize, SMEM_SZ);
        smem_set = 1;
    }
    int grid = 444;  // 3 CTAs/SM target
    if (grid > (ntiles + 3) / 4) grid = (ntiles + 3) / 4;
    mma_seg_kernel<<<grid, 128, SMEM_SZ>>>(h_node, x, W1, b1, W2, b2,
                                           num_nodes, num_dags, ntiles);

    final_kernel<<<(num_dags + 7) / 8, 256>>>(W3, b3, (float*)d_out, num_dags);
}

// round 6
// speedup vs baseline: 3.6797x; 1.2389x over previous
#include <cuda_runtime.h>
#include <cuda_bf16.h>

// DagEncoder via warp-level mma.sync (bf16 hi/lo split, 3-term).
// R5: flat node->seg map from prep (kills dependent binary search) and
// register-carried layer1->layer2 fragments (D-frag layout == A-frag layout).

#define MAX_DAGS  20000
#define MAX_NODES 2000000
__device__ float g_acc[MAX_DAGS * 64];
__device__ int   g_ptr[MAX_DAGS + 1];
__device__ int   g_seg[MAX_NODES];

typedef unsigned int u32;

__device__ __forceinline__ u32 smem_u32(const void* p) {
    u32 a;
    asm("{ .reg .u64 t; cvta.to.shared.u64 t, %1; cvt.u32.u64 %0, t; }"
        : "=r"(a) : "l"(p));
    return a;
}
__device__ __forceinline__ u32 bf16pair(float v0, float v1) {
    u32 d;
    asm("cvt.rn.bf16x2.f32 %0, %1, %2;" : "=r"(d) : "f"(v1), "f"(v0));
    return d;
}
__device__ __forceinline__ void split2(float v0, float v1, u32& hi, u32& lo) {
    hi = bf16pair(v0, v1);
    float h0 = __uint_as_float(hi << 16);
    float h1 = __uint_as_float(hi & 0xffff0000u);
    lo = bf16pair(v0 - h0, v1 - h1);
}
__device__ __forceinline__ void ldsm_x4(u32 a, u32* r) {
    asm volatile("ldmatrix.sync.aligned.m8n8.x4.shared.b16 {%0,%1,%2,%3}, [%4];"
        : "=r"(r[0]), "=r"(r[1]), "=r"(r[2]), "=r"(r[3]) : "r"(a));
}
__device__ __forceinline__ void ldsm_x4t(u32 a, u32* r) {
    asm volatile("ldmatrix.sync.aligned.m8n8.x4.trans.shared.b16 {%0,%1,%2,%3}, [%4];"
        : "=r"(r[0]), "=r"(r[1]), "=r"(r[2]), "=r"(r[3]) : "r"(a));
}
__device__ __forceinline__ void mma_bf16(float* d, const u32* a, u32 b0, u32 b1) {
    asm("mma.sync.aligned.m16n8k16.row.col.f32.bf16.bf16.f32 "
        "{%0,%1,%2,%3},{%4,%5,%6,%7},{%8,%9},{%0,%1,%2,%3};"
        : "+f"(d[0]), "+f"(d[1]), "+f"(d[2]), "+f"(d[3])
        : "r"(a[0]), "r"(a[1]), "r"(a[2]), "r"(a[3]), "r"(b0), "r"(b1));
}

// ---- prep: one warp per DAG: normalize ptr, zero acc, fill node->seg ----
__global__ void prep_kernel(const void* __restrict__ ptr_raw,
                            int num_dags, int num_nodes) {
    const int*       p32 = (const int*)ptr_raw;
    const long long* p64 = (const long long*)ptr_raw;
    const bool is32 = (p32[num_dags] == num_nodes);
    const int w = (blockIdx.x * blockDim.x + threadIdx.x) >> 5;
    const int lane = threadIdx.x & 31;
    if (w > num_dags) return;
    if (w == num_dags) { if (lane == 0) g_ptr[num_dags] = num_nodes; return; }

    const int b0 = is32 ? p32[w] : (int)p64[w];
    const int b1 = is32 ? p32[w + 1] : (int)p64[w + 1];
    if (lane == 0) g_ptr[w] = b0;
    if (lane < 16)
        ((float4*)&g_acc[(size_t)w * 64])[lane] = make_float4(0.f, 0.f, 0.f, 0.f);
    for (int i = b0 + lane; i < b1; i += 32) g_seg[i] = w;
}

// smem: W1h[48][72]b16 @0 (6912) W1l @6912, W2h[64][72] @13824 W2l @23040,
//       b1 @32256, b2 @32512; per-warp scratch 9216B @32768 + w*9216
//       (A1 hi[32][56] @0, lo @3584; later h2 hi[32][72] @0, lo @4608)
#define OFF_W1H 0
#define OFF_W1L 6912
#define OFF_W2H 13824
#define OFF_W2L 23040
#define OFF_B1  32256
#define OFF_B2  32512
#define OFF_SCR 32768
#define SCR_WARP 9216
#define SMEM_SZ (OFF_SCR + 4 * SCR_WARP)

__global__ __launch_bounds__(128) void mma_seg_kernel(
    const float* __restrict__ h_node, const float* __restrict__ x,
    const float* __restrict__ W1, const float* __restrict__ b1,
    const float* __restrict__ W2, const float* __restrict__ b2,
    int num_nodes, int num_dags, int ntiles)
{
    extern __shared__ __align__(16) unsigned char sm[];
    __shared__ int sRank[4][32];

    const int tid = threadIdx.x, lane = tid & 31, w = tid >> 5;

    for (int i = tid; i < 48 * 72; i += 128) {
        int k = i / 72, n = i % 72;
        float v = (k < 37 && n < 64) ? W1[k * 64 + n] : 0.0f;
        __nv_bfloat16 h = __float2bfloat16_rn(v);
        *(__nv_bfloat16*)(sm + OFF_W1H + i * 2) = h;
        *(__nv_bfloat16*)(sm + OFF_W1L + i * 2) =
            __float2bfloat16_rn(v - __bfloat162float(h));
    }
    for (int i = tid; i < 64 * 72; i += 128) {
        int k = i / 72, n = i % 72;
        float v = (n < 64) ? W2[k * 64 + n] : 0.0f;
        __nv_bfloat16 h = __float2bfloat16_rn(v);
        *(__nv_bfloat16*)(sm + OFF_W2H + i * 2) = h;
        *(__nv_bfloat16*)(sm + OFF_W2L + i * 2) =
            __float2bfloat16_rn(v - __bfloat162float(h));
    }
    if (tid < 64) {
        ((float*)(sm + OFF_B1))[tid] = b1[tid];
        ((float*)(sm + OFF_B2))[tid] = b2[tid];
    }
    __syncthreads();

    unsigned char* scrp = sm + OFF_SCR + w * SCR_WARP;
    const u32 scr = smem_u32(scrp);
    const u32 w1h = smem_u32(sm + OFF_W1H);
    const u32 w2h = smem_u32(sm + OFF_W2H);
    const float* B1s = (const float*)(sm + OFF_B1);
    const float* B2s = (const float*)(sm + OFF_B2);

    const int g = lane >> 2, t = lane & 3;
    const int lrow = lane & 15, lcs = lane >> 4;
    const unsigned FULL = 0xffffffffu;
    const int wid_g = blockIdx.x * 4 + w, nW = gridDim.x * 4;

    for (int tile = wid_g; tile < ntiles; tile += nW) {
        const int node0 = tile * 32;
        const int node = node0 + lane;
        const bool valid = node < num_nodes;

        float vals[48];
#pragma unroll
        for (int i = 0; i < 48; i++) vals[i] = 0.0f;
        int seg = -1;
        if (valid) {
            const float* xp = x + (size_t)node * 5;
#pragma unroll
            for (int i = 0; i < 5; i++) vals[i] = xp[i];
            const float4* hp = (const float4*)(h_node + (size_t)node * 32);
#pragma unroll
            for (int i = 0; i < 8; i++) {
                float4 v4 = hp[i];
                vals[5 + 4 * i] = v4.x; vals[6 + 4 * i] = v4.y;
                vals[7 + 4 * i] = v4.z; vals[8 + 4 * i] = v4.w;
            }
            seg = g_seg[node];
        }

        __syncwarp();  // scratch reuse vs previous iteration (h2 reads done)
        {
            u32 hi[24], lo[24];
#pragma unroll
            for (int j = 0; j < 24; j++) split2(vals[2 * j], vals[2 * j + 1], hi[j], lo[j]);
            uint4* dh = (uint4*)(scrp + lane * 112);
            uint4* dl = (uint4*)(scrp + 3584 + lane * 112);
#pragma unroll
            for (int j = 0; j < 6; j++) {
                dh[j] = make_uint4(hi[4*j], hi[4*j+1], hi[4*j+2], hi[4*j+3]);
                dl[j] = make_uint4(lo[4*j], lo[4*j+1], lo[4*j+2], lo[4*j+3]);
            }
        }
        __syncwarp();

        // ---- layer 1 A fragments (M32 K48) ----
        u32 a1h[2][3][4], a1l[2][3][4];
#pragma unroll
        for (int mt = 0; mt < 2; mt++)
#pragma unroll
            for (int kt = 0; kt < 3; kt++) {
                u32 ad = scr + (mt * 16 + lrow) * 112 + (kt * 16 + lcs * 8) * 2;
                ldsm_x4(ad, a1h[mt][kt]);
                ldsm_x4(ad + 3584, a1l[mt][kt]);
            }
        __syncwarp();  // A1 smem dead; region reused for h2 below

        // ---- layer 1 MMA; epilogue feeds layer-2 A frags IN REGISTERS ----
        u32 a2h[2][4][4], a2l[2][4][4];
#pragma unroll
        for (int half = 0; half < 2; half++) {
            float d[2][4][4];
#pragma unroll
            for (int ntl = 0; ntl < 4; ntl++) {
                float2 bb = *(const float2*)(B1s + (half * 4 + ntl) * 8 + 2 * t);
#pragma unroll
                for (int mt = 0; mt < 2; mt++) {
                    d[mt][ntl][0] = bb.x; d[mt][ntl][1] = bb.y;
                    d[mt][ntl][2] = bb.x; d[mt][ntl][3] = bb.y;
                }
            }
#pragma unroll
            for (int np = 0; np < 2; np++) {
                int npg = half * 2 + np;
                u32 bh[3][4], bl[3][4];
#pragma unroll
                for (int kt = 0; kt < 3; kt++) {
                    u32 ad = w1h + (kt * 16 + lrow) * 144 + (npg * 16 + lcs * 8) * 2;
                    ldsm_x4t(ad, bh[kt]);
                    ldsm_x4t(ad + (OFF_W1L - OFF_W1H), bl[kt]);
                }
#pragma unroll
                for (int mt = 0; mt < 2; mt++)
#pragma unroll
                    for (int kt = 0; kt < 3; kt++)
#pragma unroll
                        for (int hh = 0; hh < 2; hh++) {
                            float* dd = d[mt][np * 2 + hh];
                            mma_bf16(dd, a1h[mt][kt], bh[kt][2*hh], bh[kt][2*hh+1]);
                            mma_bf16(dd, a1h[mt][kt], bl[kt][2*hh], bl[kt][2*hh+1]);
                            mma_bf16(dd, a1l[mt][kt], bh[kt][2*hh], bh[kt][2*hh+1]);
                        }
            }
            // relu + split -> A2 fragments (D frag layout == A frag layout)
#pragma unroll
            for (int mt = 0; mt < 2; mt++)
#pragma unroll
                for (int ntl = 0; ntl < 4; ntl++) {
                    int ng = half * 4 + ntl;
                    int ktg = ng >> 1, sub = ng & 1;
                    u32 p0, q0, p1, q1;
                    split2(fmaxf(d[mt][ntl][0], 0.f), fmaxf(d[mt][ntl][1], 0.f), p0, q0);
                    split2(fmaxf(d[mt][ntl][2], 0.f), fmaxf(d[mt][ntl][3], 0.f), p1, q1);
                    a2h[mt][ktg][sub * 2 + 0] = p0;
                    a2h[mt][ktg][sub * 2 + 1] = p1;
                    a2l[mt][ktg][sub * 2 + 0] = q0;
                    a2l[mt][ktg][sub * 2 + 1] = q1;
                }
        }

        // ---- layer 2 MMA (A from registers); h2 -> smem for reduction ----
#pragma unroll
        for (int half = 0; half < 2; half++) {
            float d[2][4][4];
#pragma unroll
            for (int ntl = 0; ntl < 4; ntl++) {
                float2 bb = *(const float2*)(B2s + (half * 4 + ntl) * 8 + 2 * t);
#pragma unroll
                for (int mt = 0; mt < 2; mt++) {
                    d[mt][ntl][0] = bb.x; d[mt][ntl][1] = bb.y;
                    d[mt][ntl][2] = bb.x; d[mt][ntl][3] = bb.y;
                }
            }
#pragma unroll
            for (int np = 0; np < 2; np++) {
                int npg = half * 2 + np;
                u32 bh[4][4], bl[4][4];
#pragma unroll
                for (int kt = 0; kt < 4; kt++) {
                    u32 ad = w2h + (kt * 16 + lrow) * 144 + (npg * 16 + lcs * 8) * 2;
                    ldsm_x4t(ad, bh[kt]);
                    ldsm_x4t(ad + (OFF_W2L - OFF_W2H), bl[kt]);
                }
#pragma unroll
                for (int mt = 0; mt < 2; mt++)
#pragma unroll
                    for (int kt = 0; kt < 4; kt++)
#pragma unroll
                        for (int hh = 0; hh < 2; hh++) {
                            float* dd = d[mt][np * 2 + hh];
                            mma_bf16(dd, a2h[mt][kt], bh[kt][2*hh], bh[kt][2*hh+1]);
                            mma_bf16(dd, a2h[mt][kt], bl[kt][2*hh], bl[kt][2*hh+1]);
                            mma_bf16(dd, a2l[mt][kt], bh[kt][2*hh], bh[kt][2*hh+1]);
                        }
            }
#pragma unroll
            for (int mt = 0; mt < 2; mt++)
#pragma unroll
                for (int ntl = 0; ntl < 4; ntl++) {
                    int c = (half * 4 + ntl) * 8 + 2 * t;
                    int r0 = mt * 16 + g, r1 = r0 + 8;
                    bool ok0 = (node0 + r0) < num_nodes, ok1 = (node0 + r1) < num_nodes;
                    float v0 = ok0 ? fmaxf(d[mt][ntl][0], 0.f) : 0.f;
                    float v1 = ok0 ? fmaxf(d[mt][ntl][1], 0.f) : 0.f;
                    float v2 = ok1 ? fmaxf(d[mt][ntl][2], 0.f) : 0.f;
                    float v3 = ok1 ? fmaxf(d[mt][ntl][3], 0.f) : 0.f;
                    u32 p0, q0, p1, q1;
                    split2(v0, v1, p0, q0);
                    split2(v2, v3, p1, q1);
                    *(u32*)(scrp + r0 * 144 + c * 2) = p0;
                    *(u32*)(scrp + 4608 + r0 * 144 + c * 2) = q0;
                    *(u32*)(scrp + r1 * 144 + c * 2) = p1;
                    *(u32*)(scrp + 4608 + r1 * 144 + c * 2) = q1;
                }
        }
        __syncwarp();

        // ---- segment ranks + indicator fragments ----
        int segup = __shfl_up_sync(FULL, seg, 1);
        bool head = valid && (lane == 0 || segup != seg);
        unsigned bm = __ballot_sync(FULL, head);
        int rank = __popc(bm & (0xffffffffu >> (31 - lane))) - 1;
        int nsegs = __popc(bm);
        if (head) sRank[w][rank] = seg;
        __syncwarp();

        int rk[2][4];
#pragma unroll
        for (int kt = 0; kt < 2; kt++) {
            rk[kt][0] = __shfl_sync(FULL, rank, kt * 16 + 2 * t);
            rk[kt][1] = __shfl_sync(FULL, rank, kt * 16 + 2 * t + 1);
            rk[kt][2] = __shfl_sync(FULL, rank, kt * 16 + 8 + 2 * t);
            rk[kt][3] = __shfl_sync(FULL, rank, kt * 16 + 8 + 2 * t + 1);
        }
        const int nmt = (nsegs > 16) ? 2 : 1;
        u32 ia[2][2][4];
#pragma unroll
        for (int mt = 0; mt < 2; mt++)
#pragma unroll
            for (int kt = 0; kt < 2; kt++) {
                int R0 = mt * 16 + g, R1 = R0 + 8;
                ia[mt][kt][0] = (rk[kt][0]==R0 ? 0x3F80u:0u) | (rk[kt][1]==R0 ? 0x3F800000u:0u);
                ia[mt][kt][1] = (rk[kt][0]==R1 ? 0x3F80u:0u) | (rk[kt][1]==R1 ? 0x3F800000u:0u);
                ia[mt][kt][2] = (rk[kt][2]==R0 ? 0x3F80u:0u) | (rk[kt][3]==R0 ? 0x3F800000u:0u);
                ia[mt][kt][3] = (rk[kt][2]==R1 ? 0x3F80u:0u) | (rk[kt][3]==R1 ? 0x3F800000u:0u);
            }

        // ---- reduction MMA: D[rank][n] = I @ h2 (hi + lo) ----
        float dr[2][8][4];
#pragma unroll
        for (int mt = 0; mt < 2; mt++)
#pragma unroll
            for (int ntl = 0; ntl < 8; ntl++)
#pragma unroll
                for (int q = 0; q < 4; q++) dr[mt][ntl][q] = 0.0f;

#pragma unroll
        for (int np = 0; np < 4; np++) {
            u32 bh[2][4], bl[2][4];
#pragma unroll
            for (int kt = 0; kt < 2; kt++) {
                u32 ad = scr + (kt * 16 + lrow) * 144 + (np * 16 + lcs * 8) * 2;
                ldsm_x4t(ad, bh[kt]);
                ldsm_x4t(ad + 4608, bl[kt]);
            }
            for (int mt = 0; mt < nmt; mt++)
#pragma unroll
                for (int kt = 0; kt < 2; kt++)
#pragma unroll
                    for (int hh = 0; hh < 2; hh++) {
                        float* dd = dr[mt][np * 2 + hh];
                        mma_bf16(dd, ia[mt][kt], bh[kt][2*hh], bh[kt][2*hh+1]);
                        mma_bf16(dd, ia[mt][kt], bl[kt][2*hh], bl[kt][2*hh+1]);
                    }
        }

        // ---- scatter per-segment sums ----
        for (int mt = 0; mt < nmt; mt++)
#pragma unroll
            for (int ntl = 0; ntl < 8; ntl++) {
                int c = ntl * 8 + 2 * t;
                int R0 = mt * 16 + g, R1 = R0 + 8;
                if (R0 < nsegs) {
                    float* p = &g_acc[(size_t)sRank[w][R0] * 64 + c];
                    atomicAdd(p, dr[mt][ntl][0]);
                    atomicAdd(p + 1, dr[mt][ntl][1]);
                }
                if (R1 < nsegs) {
                    float* p = &g_acc[(size_t)sRank[w][R1] * 64 + c];
                    atomicAdd(p, dr[mt][ntl][2]);
                    atomicAdd(p + 1, dr[mt][ntl][3]);
                }
            }
    }
}

__global__ __launch_bounds__(256) void final_kernel(
    const float* __restrict__ W3, const float* __restrict__ b3,
    float* __restrict__ out, int num_dags)
{
    __shared__ __align__(16) float sW3[64 * 32];
    __shared__ float sB3[32];
    const int tid = threadIdx.x;
    for (int i = tid; i < 64 * 32; i += 256) sW3[i] = W3[i];
    if (tid < 32) sB3[tid] = b3[tid];
    __syncthreads();

    const int d = blockIdx.x * 8 + (tid >> 5);
    const int e = tid & 31;
    if (d >= num_dags) return;

    const float cnt = (float)(g_ptr[d + 1] - g_ptr[d]);
    float acc = cnt * sB3[e];
    const float* gd = &g_acc[(size_t)d * 64];
#pragma unroll
    for (int k = 0; k < 64; k++)
        acc = fmaf(gd[k], sW3[k * 32 + e], acc);
    out[(size_t)d * 32 + e] = acc;
}

extern "C" void kernel_launch(void* const* d_in, const int* in_sizes, int n_in,
                              void* d_out, int out_size)
{
    const float* h_node = (const float*)d_in[0];
    const float* x      = (const float*)d_in[1];
    const float* W1     = (const float*)d_in[2];
    const float* b1     = (const float*)d_in[3];
    const float* W2     = (const float*)d_in[4];
    const float* b2     = (const float*)d_in[5];
    const float* W3     = (const float*)d_in[6];
    const float* b3     = (const float*)d_in[7];
    const void*  ptr    = (const void*)d_in[8];

    const int num_nodes = in_sizes[0] / 32;
    const int num_dags  = in_sizes[8] - 1;
    const int ntiles    = (num_nodes + 31) / 32;

    const int prep_warps = num_dags + 1;
    prep_kernel<<<(prep_warps * 32 + 255) / 256, 256>>>(ptr, num_dags, num_nodes);

    static int smem_set = 0;
    if (!smem_set) {
        cudaFuncSetAttribute(mma_seg_kernel,
                             cudaFuncAttributeMaxDynamicSharedMemorySize, SMEM_SZ);
        smem_set = 1;
    }
    int grid = 444;
    if (grid > (ntiles + 3) / 4) grid = (ntiles + 3) / 4;
    mma_seg_kernel<<<grid, 128, SMEM_SZ>>>(h_node, x, W1, b1, W2, b2,
                                           num_nodes, num_dags, ntiles);

    final_kernel<<<(num_dags + 7) / 8, 256>>>(W3, b3, (float*)d_out, num_dags);
}

// round 7
// speedup vs baseline: 4.4954x; 1.2217x over previous
#include <cuda_runtime.h>
#include <cuda_bf16.h>

// DagEncoder via warp-level mma.sync (bf16 hi/lo split, 3-term).
// R6: tiles with <=2 segments (97%) reduce via fp32 shfl colsum in registers
// (no h2 quantization, no indicator MMA); >=3 segs keep the MMA fallback.

#define MAX_DAGS  20000
#define MAX_NODES 2000000
__device__ float g_acc[MAX_DAGS * 64];
__device__ int   g_ptr[MAX_DAGS + 1];
__device__ int   g_seg[MAX_NODES];

typedef unsigned int u32;

__device__ __forceinline__ u32 smem_u32(const void* p) {
    u32 a;
    asm("{ .reg .u64 t; cvta.to.shared.u64 t, %1; cvt.u32.u64 %0, t; }"
        : "=r"(a) : "l"(p));
    return a;
}
__device__ __forceinline__ u32 bf16pair(float v0, float v1) {
    u32 d;
    asm("cvt.rn.bf16x2.f32 %0, %1, %2;" : "=r"(d) : "f"(v1), "f"(v0));
    return d;
}
__device__ __forceinline__ void split2(float v0, float v1, u32& hi, u32& lo) {
    hi = bf16pair(v0, v1);
    float h0 = __uint_as_float(hi << 16);
    float h1 = __uint_as_float(hi & 0xffff0000u);
    lo = bf16pair(v0 - h0, v1 - h1);
}
__device__ __forceinline__ void ldsm_x4(u32 a, u32* r) {
    asm volatile("ldmatrix.sync.aligned.m8n8.x4.shared.b16 {%0,%1,%2,%3}, [%4];"
        : "=r"(r[0]), "=r"(r[1]), "=r"(r[2]), "=r"(r[3]) : "r"(a));
}
__device__ __forceinline__ void ldsm_x4t(u32 a, u32* r) {
    asm volatile("ldmatrix.sync.aligned.m8n8.x4.trans.shared.b16 {%0,%1,%2,%3}, [%4];"
        : "=r"(r[0]), "=r"(r[1]), "=r"(r[2]), "=r"(r[3]) : "r"(a));
}
__device__ __forceinline__ void mma_bf16(float* d, const u32* a, u32 b0, u32 b1) {
    asm("mma.sync.aligned.m16n8k16.row.col.f32.bf16.bf16.f32 "
        "{%0,%1,%2,%3},{%4,%5,%6,%7},{%8,%9},{%0,%1,%2,%3};"
        : "+f"(d[0]), "+f"(d[1]), "+f"(d[2]), "+f"(d[3])
        : "r"(a[0]), "r"(a[1]), "r"(a[2]), "r"(a[3]), "r"(b0), "r"(b1));
}

// ---- prep: one warp per DAG: normalize ptr, zero acc, fill node->seg ----
__global__ void prep_kernel(const void* __restrict__ ptr_raw,
                            int num_dags, int num_nodes) {
    const int*       p32 = (const int*)ptr_raw;
    const long long* p64 = (const long long*)ptr_raw;
    const bool is32 = (p32[num_dags] == num_nodes);
    const int w = (blockIdx.x * blockDim.x + threadIdx.x) >> 5;
    const int lane = threadIdx.x & 31;
    if (w > num_dags) return;
    if (w == num_dags) { if (lane == 0) g_ptr[num_dags] = num_nodes; return; }

    const int b0 = is32 ? p32[w] : (int)p64[w];
    const int b1 = is32 ? p32[w + 1] : (int)p64[w + 1];
    if (lane == 0) g_ptr[w] = b0;
    if (lane < 16)
        ((float4*)&g_acc[(size_t)w * 64])[lane] = make_float4(0.f, 0.f, 0.f, 0.f);
    for (int i = b0 + lane; i < b1; i += 32) g_seg[i] = w;
}

// smem: W1h[48][72]b16 @0 (6912) W1l @6912, W2h[64][72] @13824 W2l @23040,
//       b1 @32256, b2 @32512; per-warp scratch 9216B @32768 + w*9216
#define OFF_W1H 0
#define OFF_W1L 6912
#define OFF_W2H 13824
#define OFF_W2L 23040
#define OFF_B1  32256
#define OFF_B2  32512
#define OFF_SCR 32768
#define SCR_WARP 9216
#define SMEM_SZ (OFF_SCR + 4 * SCR_WARP)

__global__ __launch_bounds__(128) void mma_seg_kernel(
    const float* __restrict__ h_node, const float* __restrict__ x,
    const float* __restrict__ W1, const float* __restrict__ b1,
    const float* __restrict__ W2, const float* __restrict__ b2,
    int num_nodes, int num_dags, int ntiles)
{
    extern __shared__ __align__(16) unsigned char sm[];
    __shared__ int sRank[4][32];

    const int tid = threadIdx.x, lane = tid & 31, w = tid >> 5;

    for (int i = tid; i < 48 * 72; i += 128) {
        int k = i / 72, n = i % 72;
        float v = (k < 37 && n < 64) ? W1[k * 64 + n] : 0.0f;
        __nv_bfloat16 h = __float2bfloat16_rn(v);
        *(__nv_bfloat16*)(sm + OFF_W1H + i * 2) = h;
        *(__nv_bfloat16*)(sm + OFF_W1L + i * 2) =
            __float2bfloat16_rn(v - __bfloat162float(h));
    }
    for (int i = tid; i < 64 * 72; i += 128) {
        int k = i / 72, n = i % 72;
        float v = (n < 64) ? W2[k * 64 + n] : 0.0f;
        __nv_bfloat16 h = __float2bfloat16_rn(v);
        *(__nv_bfloat16*)(sm + OFF_W2H + i * 2) = h;
        *(__nv_bfloat16*)(sm + OFF_W2L + i * 2) =
            __float2bfloat16_rn(v - __bfloat162float(h));
    }
    if (tid < 64) {
        ((float*)(sm + OFF_B1))[tid] = b1[tid];
        ((float*)(sm + OFF_B2))[tid] = b2[tid];
    }
    __syncthreads();

    unsigned char* scrp = sm + OFF_SCR + w * SCR_WARP;
    const u32 scr = smem_u32(scrp);
    const u32 w1h = smem_u32(sm + OFF_W1H);
    const u32 w2h = smem_u32(sm + OFF_W2H);
    const float* B1s = (const float*)(sm + OFF_B1);
    const float* B2s = (const float*)(sm + OFF_B2);

    const int g = lane >> 2, t = lane & 3;
    const int lrow = lane & 15, lcs = lane >> 4;
    const unsigned FULL = 0xffffffffu;
    const int wid_g = blockIdx.x * 4 + w, nW = gridDim.x * 4;

    for (int tile = wid_g; tile < ntiles; tile += nW) {
        const int node0 = tile * 32;
        const int node = node0 + lane;
        const bool valid = node < num_nodes;

        float vals[48];
#pragma unroll
        for (int i = 0; i < 48; i++) vals[i] = 0.0f;
        int seg = -1;
        if (valid) {
            const float* xp = x + (size_t)node * 5;
#pragma unroll
            for (int i = 0; i < 5; i++) vals[i] = xp[i];
            const float4* hp = (const float4*)(h_node + (size_t)node * 32);
#pragma unroll
            for (int i = 0; i < 8; i++) {
                float4 v4 = hp[i];
                vals[5 + 4 * i] = v4.x; vals[6 + 4 * i] = v4.y;
                vals[7 + 4 * i] = v4.z; vals[8 + 4 * i] = v4.w;
            }
            seg = g_seg[node];
        }

        // ---- early segment classification ----
        int segup = __shfl_up_sync(FULL, seg, 1);
        bool head = valid && (lane == 0 || segup != seg);
        unsigned bm = __ballot_sync(FULL, head);
        int rank = __popc(bm & (0xffffffffu >> (31 - lane))) - 1;
        const int nsegs = __popc(bm);
        if (head) sRank[w][rank] = seg;

        int segA = 0, segB = 0, rowb = 32;
        if (nsegs > 0) segA = __shfl_sync(FULL, seg, __ffs(bm) - 1);
        if (nsegs >= 2) {
            unsigned bm2 = bm & (bm - 1);
            rowb = __ffs(bm2) - 1;
            segB = __shfl_sync(FULL, seg, rowb);
        }
        const bool fast = (nsegs <= 2);

        __syncwarp();  // scratch reuse + sRank visibility
        {
            u32 hi[24], lo[24];
#pragma unroll
            for (int j = 0; j < 24; j++) split2(vals[2 * j], vals[2 * j + 1], hi[j], lo[j]);
            uint4* dh = (uint4*)(scrp + lane * 112);
            uint4* dl = (uint4*)(scrp + 3584 + lane * 112);
#pragma unroll
            for (int j = 0; j < 6; j++) {
                dh[j] = make_uint4(hi[4*j], hi[4*j+1], hi[4*j+2], hi[4*j+3]);
                dl[j] = make_uint4(lo[4*j], lo[4*j+1], lo[4*j+2], lo[4*j+3]);
            }
        }
        __syncwarp();

        // ---- layer 1 A fragments (M32 K48) ----
        u32 a1h[2][3][4], a1l[2][3][4];
#pragma unroll
        for (int mt = 0; mt < 2; mt++)
#pragma unroll
            for (int kt = 0; kt < 3; kt++) {
                u32 ad = scr + (mt * 16 + lrow) * 112 + (kt * 16 + lcs * 8) * 2;
                ldsm_x4(ad, a1h[mt][kt]);
                ldsm_x4(ad + 3584, a1l[mt][kt]);
            }
        __syncwarp();  // A1 smem dead

        // ---- layer 1 MMA -> layer-2 A frags in registers ----
        u32 a2h[2][4][4], a2l[2][4][4];
#pragma unroll
        for (int half = 0; half < 2; half++) {
            float d[2][4][4];
#pragma unroll
            for (int ntl = 0; ntl < 4; ntl++) {
                float2 bb = *(const float2*)(B1s + (half * 4 + ntl) * 8 + 2 * t);
#pragma unroll
                for (int mt = 0; mt < 2; mt++) {
                    d[mt][ntl][0] = bb.x; d[mt][ntl][1] = bb.y;
                    d[mt][ntl][2] = bb.x; d[mt][ntl][3] = bb.y;
                }
            }
#pragma unroll
            for (int np = 0; np < 2; np++) {
                int npg = half * 2 + np;
                u32 bh[3][4], bl[3][4];
#pragma unroll
                for (int kt = 0; kt < 3; kt++) {
                    u32 ad = w1h + (kt * 16 + lrow) * 144 + (npg * 16 + lcs * 8) * 2;
                    ldsm_x4t(ad, bh[kt]);
                    ldsm_x4t(ad + (OFF_W1L - OFF_W1H), bl[kt]);
                }
#pragma unroll
                for (int mt = 0; mt < 2; mt++)
#pragma unroll
                    for (int kt = 0; kt < 3; kt++)
#pragma unroll
                        for (int hh = 0; hh < 2; hh++) {
                            float* dd = d[mt][np * 2 + hh];
                            mma_bf16(dd, a1h[mt][kt], bh[kt][2*hh], bh[kt][2*hh+1]);
                            mma_bf16(dd, a1h[mt][kt], bl[kt][2*hh], bl[kt][2*hh+1]);
                            mma_bf16(dd, a1l[mt][kt], bh[kt][2*hh], bh[kt][2*hh+1]);
                        }
            }
#pragma unroll
            for (int mt = 0; mt < 2; mt++)
#pragma unroll
                for (int ntl = 0; ntl < 4; ntl++) {
                    int ng = half * 4 + ntl;
                    int ktg = ng >> 1, sub = ng & 1;
                    u32 p0, q0, p1, q1;
                    split2(fmaxf(d[mt][ntl][0], 0.f), fmaxf(d[mt][ntl][1], 0.f), p0, q0);
                    split2(fmaxf(d[mt][ntl][2], 0.f), fmaxf(d[mt][ntl][3], 0.f), p1, q1);
                    a2h[mt][ktg][sub * 2 + 0] = p0;
                    a2h[mt][ktg][sub * 2 + 1] = p1;
                    a2l[mt][ktg][sub * 2 + 0] = q0;
                    a2l[mt][ktg][sub * 2 + 1] = q1;
                }
        }

        // ---- layer 2 MMA; epilogue: fast colsum reduce OR smem for MMA ----
#pragma unroll
        for (int half = 0; half < 2; half++) {
            float d[2][4][4];
#pragma unroll
            for (int ntl = 0; ntl < 4; ntl++) {
                float2 bb = *(const float2*)(B2s + (half * 4 + ntl) * 8 + 2 * t);
#pragma unroll
                for (int mt = 0; mt < 2; mt++) {
                    d[mt][ntl][0] = bb.x; d[mt][ntl][1] = bb.y;
                    d[mt][ntl][2] = bb.x; d[mt][ntl][3] = bb.y;
                }
            }
#pragma unroll
            for (int np = 0; np < 2; np++) {
                int npg = half * 2 + np;
                u32 bh[4][4], bl[4][4];
#pragma unroll
                for (int kt = 0; kt < 4; kt++) {
                    u32 ad = w2h + (kt * 16 + lrow) * 144 + (npg * 16 + lcs * 8) * 2;
                    ldsm_x4t(ad, bh[kt]);
                    ldsm_x4t(ad + (OFF_W2L - OFF_W2H), bl[kt]);
                }
#pragma unroll
                for (int mt = 0; mt < 2; mt++)
#pragma unroll
                    for (int kt = 0; kt < 4; kt++)
#pragma unroll
                        for (int hh = 0; hh < 2; hh++) {
                            float* dd = d[mt][np * 2 + hh];
                            mma_bf16(dd, a2h[mt][kt], bh[kt][2*hh], bh[kt][2*hh+1]);
                            mma_bf16(dd, a2h[mt][kt], bl[kt][2*hh], bl[kt][2*hh+1]);
                            mma_bf16(dd, a2l[mt][kt], bh[kt][2*hh], bh[kt][2*hh+1]);
                        }
            }

            // relu + validity zero (in place)
#pragma unroll
            for (int mt = 0; mt < 2; mt++)
#pragma unroll
                for (int ntl = 0; ntl < 4; ntl++) {
                    bool ok0 = (node0 + mt * 16 + g) < num_nodes;
                    bool ok1 = (node0 + mt * 16 + g + 8) < num_nodes;
                    d[mt][ntl][0] = ok0 ? fmaxf(d[mt][ntl][0], 0.f) : 0.f;
                    d[mt][ntl][1] = ok0 ? fmaxf(d[mt][ntl][1], 0.f) : 0.f;
                    d[mt][ntl][2] = ok1 ? fmaxf(d[mt][ntl][2], 0.f) : 0.f;
                    d[mt][ntl][3] = ok1 ? fmaxf(d[mt][ntl][3], 0.f) : 0.f;
                }

            if (fast) {
                if (nsegs > 0) {
#pragma unroll
                    for (int ntl = 0; ntl < 4; ntl++) {
                        float sA0 = 0.f, sA1 = 0.f, sB0 = 0.f, sB1 = 0.f;
#pragma unroll
                        for (int mt = 0; mt < 2; mt++) {
                            int r0 = mt * 16 + g, r1 = r0 + 8;
                            if (r0 < rowb) { sA0 += d[mt][ntl][0]; sA1 += d[mt][ntl][1]; }
                            else           { sB0 += d[mt][ntl][0]; sB1 += d[mt][ntl][1]; }
                            if (r1 < rowb) { sA0 += d[mt][ntl][2]; sA1 += d[mt][ntl][3]; }
                            else           { sB0 += d[mt][ntl][2]; sB1 += d[mt][ntl][3]; }
                        }
#pragma unroll
                        for (int m = 4; m <= 16; m <<= 1) {
                            sA0 += __shfl_xor_sync(FULL, sA0, m);
                            sA1 += __shfl_xor_sync(FULL, sA1, m);
                        }
                        if (nsegs == 2) {
#pragma unroll
                            for (int m = 4; m <= 16; m <<= 1) {
                                sB0 += __shfl_xor_sync(FULL, sB0, m);
                                sB1 += __shfl_xor_sync(FULL, sB1, m);
                            }
                        }
                        if (g == 0) {
                            int c = half * 32 + ntl * 8 + 2 * t;
                            atomicAdd(&g_acc[(size_t)segA * 64 + c], sA0);
                            atomicAdd(&g_acc[(size_t)segA * 64 + c + 1], sA1);
                            if (nsegs == 2) {
                                atomicAdd(&g_acc[(size_t)segB * 64 + c], sB0);
                                atomicAdd(&g_acc[(size_t)segB * 64 + c + 1], sB1);
                            }
                        }
                    }
                }
            } else {
                // stash h2 (split) into smem for the indicator MMA
#pragma unroll
                for (int mt = 0; mt < 2; mt++)
#pragma unroll
                    for (int ntl = 0; ntl < 4; ntl++) {
                        int c = (half * 4 + ntl) * 8 + 2 * t;
                        int r0 = mt * 16 + g, r1 = r0 + 8;
                        u32 p0, q0, p1, q1;
                        split2(d[mt][ntl][0], d[mt][ntl][1], p0, q0);
                        split2(d[mt][ntl][2], d[mt][ntl][3], p1, q1);
                        *(u32*)(scrp + r0 * 144 + c * 2) = p0;
                        *(u32*)(scrp + 4608 + r0 * 144 + c * 2) = q0;
                        *(u32*)(scrp + r1 * 144 + c * 2) = p1;
                        *(u32*)(scrp + 4608 + r1 * 144 + c * 2) = q1;
                    }
            }
        }

        if (!fast) {
            __syncwarp();
            int rk[2][4];
#pragma unroll
            for (int kt = 0; kt < 2; kt++) {
                rk[kt][0] = __shfl_sync(FULL, rank, kt * 16 + 2 * t);
                rk[kt][1] = __shfl_sync(FULL, rank, kt * 16 + 2 * t + 1);
                rk[kt][2] = __shfl_sync(FULL, rank, kt * 16 + 8 + 2 * t);
                rk[kt][3] = __shfl_sync(FULL, rank, kt * 16 + 8 + 2 * t + 1);
            }
            const int nmt = (nsegs > 16) ? 2 : 1;
            u32 ia[2][2][4];
#pragma unroll
            for (int mt = 0; mt < 2; mt++)
#pragma unroll
                for (int kt = 0; kt < 2; kt++) {
                    int R0 = mt * 16 + g, R1 = R0 + 8;
                    ia[mt][kt][0] = (rk[kt][0]==R0 ? 0x3F80u:0u) | (rk[kt][1]==R0 ? 0x3F800000u:0u);
                    ia[mt][kt][1] = (rk[kt][0]==R1 ? 0x3F80u:0u) | (rk[kt][1]==R1 ? 0x3F800000u:0u);
                    ia[mt][kt][2] = (rk[kt][2]==R0 ? 0x3F80u:0u) | (rk[kt][3]==R0 ? 0x3F800000u:0u);
                    ia[mt][kt][3] = (rk[kt][2]==R1 ? 0x3F80u:0u) | (rk[kt][3]==R1 ? 0x3F800000u:0u);
                }

            float dr[2][8][4];
#pragma unroll
            for (int mt = 0; mt < 2; mt++)
#pragma unroll
                for (int ntl = 0; ntl < 8; ntl++)
#pragma unroll
                    for (int q = 0; q < 4; q++) dr[mt][ntl][q] = 0.0f;

#pragma unroll
            for (int np = 0; np < 4; np++) {
                u32 bh[2][4], bl[2][4];
#pragma unroll
                for (int kt = 0; kt < 2; kt++) {
                    u32 ad = scr + (kt * 16 + lrow) * 144 + (np * 16 + lcs * 8) * 2;
                    ldsm_x4t(ad, bh[kt]);
                    ldsm_x4t(ad + 4608, bl[kt]);
                }
                for (int mt = 0; mt < nmt; mt++)
#pragma unroll
                    for (int kt = 0; kt < 2; kt++)
#pragma unroll
                        for (int hh = 0; hh < 2; hh++) {
                            float* dd = dr[mt][np * 2 + hh];
                            mma_bf16(dd, ia[mt][kt], bh[kt][2*hh], bh[kt][2*hh+1]);
                            mma_bf16(dd, ia[mt][kt], bl[kt][2*hh], bl[kt][2*hh+1]);
                        }
            }

            for (int mt = 0; mt < nmt; mt++)
#pragma unroll
                for (int ntl = 0; ntl < 8; ntl++) {
                    int c = ntl * 8 + 2 * t;
                    int R0 = mt * 16 + g, R1 = R0 + 8;
                    if (R0 < nsegs) {
                        float* p = &g_acc[(size_t)sRank[w][R0] * 64 + c];
                        atomicAdd(p, dr[mt][ntl][0]);
                        atomicAdd(p + 1, dr[mt][ntl][1]);
                    }
                    if (R1 < nsegs) {
                        float* p = &g_acc[(size_t)sRank[w][R1] * 64 + c];
                        atomicAdd(p, dr[mt][ntl][2]);
                        atomicAdd(p + 1, dr[mt][ntl][3]);
                    }
                }
        }
    }
}

__global__ __launch_bounds__(256) void final_kernel(
    const float* __restrict__ W3, const float* __restrict__ b3,
    float* __restrict__ out, int num_dags)
{
    __shared__ __align__(16) float sW3[64 * 32];
    __shared__ float sB3[32];
    const int tid = threadIdx.x;
    for (int i = tid; i < 64 * 32; i += 256) sW3[i] = W3[i];
    if (tid < 32) sB3[tid] = b3[tid];
    __syncthreads();

    const int d = blockIdx.x * 8 + (tid >> 5);
    const int e = tid & 31;
    if (d >= num_dags) return;

    const float cnt = (float)(g_ptr[d + 1] - g_ptr[d]);
    float acc = cnt * sB3[e];
    const float* gd = &g_acc[(size_t)d * 64];
#pragma unroll
    for (int k = 0; k < 64; k++)
        acc = fmaf(gd[k], sW3[k * 32 + e], acc);
    out[(size_t)d * 32 + e] = acc;
}

extern "C" void kernel_launch(void* const* d_in, const int* in_sizes, int n_in,
                              void* d_out, int out_size)
{
    const float* h_node = (const float*)d_in[0];
    const float* x      = (const float*)d_in[1];
    const float* W1     = (const float*)d_in[2];
    const float* b1     = (const float*)d_in[3];
    const float* W2     = (const float*)d_in[4];
    const float* b2     = (const float*)d_in[5];
    const float* W3     = (const float*)d_in[6];
    const float* b3     = (const float*)d_in[7];
    const void*  ptr    = (const void*)d_in[8];

    const int num_nodes = in_sizes[0] / 32;
    const int num_dags  = in_sizes[8] - 1;
    const int ntiles    = (num_nodes + 31) / 32;

    const int prep_warps = num_dags + 1;
    prep_kernel<<<(prep_warps * 32 + 255) / 256, 256>>>(ptr, num_dags, num_nodes);

    static int smem_set = 0;
    if (!smem_set) {
        cudaFuncSetAttribute(mma_seg_kernel,
                             cudaFuncAttributeMaxDynamicSharedMemorySize, SMEM_SZ);
        smem_set = 1;
    }
    int grid = 444;
    if (grid > (ntiles + 3) / 4) grid = (ntiles + 3) / 4;
    mma_seg_kernel<<<grid, 128, SMEM_SZ>>>(h_node, x, W1, b1, W2, b2,
                                           num_nodes, num_dags, ntiles);

    final_kernel<<<(num_dags + 7) / 8, 256>>>(W3, b3, (float*)d_out, num_dags);
}